// round 8
// baseline (speedup 1.0000x reference)
#include <cuda_runtime.h>
#include <math.h>
#include <stdint.h>

#define NN 50000
#define EE 400000
#define FF 128
#define F3 384
#define NRBF 20
#define EPAD (EE + NN)
#define EP 450560
#define CHUNK 32

typedef unsigned long long u64;

// ---------------- f32x2 packed helpers ----------------
__device__ __forceinline__ u64 pk2(float a, float b) {
    u64 r; asm("mov.b64 %0,{%1,%2};" : "=l"(r) : "f"(a), "f"(b)); return r;
}
__device__ __forceinline__ u64 pkdup(float a) {
    u64 r; asm("mov.b64 %0,{%1,%1};" : "=l"(r) : "f"(a)); return r;
}
__device__ __forceinline__ float2 upk(u64 v) {
    float2 f; asm("mov.b64 {%0,%1},%2;" : "=f"(f.x), "=f"(f.y) : "l"(v)); return f;
}
__device__ __forceinline__ u64 f2fma(u64 a, u64 b, u64 c) {
    u64 d; asm("fma.rn.f32x2 %0,%1,%2,%3;" : "=l"(d) : "l"(a), "l"(b), "l"(c)); return d;
}
__device__ __forceinline__ u64 f2add(u64 a, u64 b) {
    u64 d; asm("add.rn.f32x2 %0,%1,%2;" : "=l"(d) : "l"(a), "l"(b)); return d;
}

// ---------------- tf32 helpers ----------------
__device__ __forceinline__ float to_tf32f(float f) {
    uint32_t u; asm("cvt.rna.tf32.f32 %0, %1;" : "=r"(u) : "f"(f));
    return __uint_as_float(u);
}
__device__ __forceinline__ void mma_tf32(float c[4], const float4& a, const float2& b) {
    asm("mma.sync.aligned.m16n8k8.row.col.f32.tf32.tf32.f32 "
        "{%0,%1,%2,%3},{%4,%5,%6,%7},{%8,%9},{%0,%1,%2,%3};"
        : "+f"(c[0]), "+f"(c[1]), "+f"(c[2]), "+f"(c[3])
        : "r"(__float_as_uint(a.x)), "r"(__float_as_uint(a.y)),
          "r"(__float_as_uint(a.z)), "r"(__float_as_uint(a.w)),
          "r"(__float_as_uint(b.x)), "r"(__float_as_uint(b.y)));
}

// ---------------- scratch ----------------
__device__ float g_phi[NN * F3];
__device__ float g_h[NN * FF];
__device__ float g_rbf[NRBF * EP];
__device__ float g_dirx[EP];
__device__ float g_diry[EP];
__device__ float g_dirz[EP];
__device__ int   g_cnt[NN];
__device__ int   g_off[NN];
__device__ int   g_cur[NN];
__device__ int   g_order[EPAD];

// ---------------- CSR build ----------------
__global__ void k_init() {
    int i = blockIdx.x * blockDim.x + threadIdx.x;
    if (i < NN) g_cnt[i] = 0;
    if (i < EPAD) g_order[i] = -1;
}

__global__ void k_hist(const float* __restrict__ r) {
    int e = blockIdx.x * blockDim.x + threadIdx.x;
    if (e < EE) {
        int j = (int)r[e * 5 + 1];
        atomicAdd(&g_cnt[j], 1);
    }
}

__global__ void k_scan() {
    __shared__ int part[1024];
    int t = threadIdx.x;
    const int CH = (NN + 1023) / 1024;
    int base = t * CH, sum = 0;
    for (int i = 0; i < CH; i++) {
        int idx = base + i;
        if (idx < NN) sum += (g_cnt[idx] + 1) & ~1;
    }
    part[t] = sum;
    __syncthreads();
    for (int off = 1; off < 1024; off <<= 1) {
        int v = (t >= off) ? part[t - off] : 0;
        __syncthreads();
        part[t] += v;
        __syncthreads();
    }
    int run = (t > 0) ? part[t - 1] : 0;
    for (int i = 0; i < CH; i++) {
        int idx = base + i;
        if (idx < NN) {
            g_off[idx] = run;
            g_cur[idx] = run;
            run += (g_cnt[idx] + 1) & ~1;
        }
    }
}

__global__ void k_fill(const float* __restrict__ r) {
    int e = blockIdx.x * blockDim.x + threadIdx.x;
    if (e < EE) {
        int j = (int)r[e * 5 + 1];
        int pos = atomicAdd(&g_cur[j], 1);
        g_order[pos] = e;
    }
}

__global__ void k_sortlists() {
    int n = blockIdx.x * blockDim.x + threadIdx.x;
    if (n >= NN) return;
    int s0 = g_off[n], s1 = s0 + g_cnt[n];
    for (int i = s0 + 1; i < s1; i++) {
        int key = g_order[i];
        int j = i - 1;
        while (j >= s0 && g_order[j] > key) {
            g_order[j + 1] = g_order[j];
            j--;
        }
        g_order[j + 1] = key;
    }
}

// ---------------- per-edge precompute ----------------
__global__ void k_edge(const float* __restrict__ r) {
    int p = blockIdx.x * blockDim.x + threadIdx.x;
    if (p >= EPAD) return;
    int eid = g_order[p];
    if (eid < 0) {
#pragma unroll
        for (int k = 0; k < NRBF; k++) g_rbf[k * EP + p] = 0.0f;
        g_dirx[p] = 0.0f; g_diry[p] = 0.0f; g_dirz[p] = 0.0f;
        return;
    }
    float rx = r[eid * 5 + 2];
    float ry = r[eid * 5 + 3];
    float rz = r[eid * 5 + 4];
    float z = fabsf(rz);
    float inv = 1.0f / (z + 1e-8f);
    float th = 0.6283185307179586f * z;
    float s, c;
    sincosf(th, &s, &c);
    float twoc = 2.0f * c;
    float skm = 0.0f, sk = s;
#pragma unroll
    for (int k = 0; k < NRBF; k++) {
        g_rbf[k * EP + p] = sk * inv;
        float nxt = fmaf(twoc, sk, -skm);
        skm = sk; sk = nxt;
    }
    float nrm = sqrtf(rx * rx + ry * ry + rz * rz);
    float invn = 1.0f / (nrm + 1e-8f);
    g_dirx[p] = rx * invn;
    g_diry[p] = ry * invn;
    g_dirz[p] = rz * invn;
}

// ---------------- 3xTF32 tensor GEMM: fragment-major smem + double buffer ----------------
// BM=128, BN=64, BK=16; 256 threads = 8 warps (4m x 2n), warp tile 32x32.
template <bool SILU>
__global__ void __launch_bounds__(256) k_gemm_tc(const float* __restrict__ A,
                                                 const float* __restrict__ B,
                                                 const float* __restrict__ bias,
                                                 float* __restrict__ C,
                                                 int M, int N, int K) {
    // fragment-major stages: A: [ks*8+mt][lane][4] = 16*32*4 floats; B: [ks*8+nt][lane][2]
    __shared__ __align__(16) float AfH[2][2048];
    __shared__ __align__(16) float AfL[2][2048];
    __shared__ __align__(16) float BfH[2][1024];
    __shared__ __align__(16) float BfL[2][1024];

    int t = threadIdx.x;
    int lane = t & 31;
    int wid = t >> 5;
    int warp_m = wid >> 1;
    int warp_n = wid & 1;
    int qrow = lane >> 2;
    int qcol = lane & 3;

    int rowBase = blockIdx.y * 128;
    int colBase = blockIdx.x * 64;

    // ---- staging constants ----
    // A: thread loads 2 float4 rows-of-4k
    int arow[2], abase[2];
#pragma unroll
    for (int h = 0; h < 2; h++) {
        int slot = t * 2 + h;            // 0..511
        int row = slot >> 2;             // 0..127
        int kq = (slot & 3) << 2;        // 0,4,8,12
        int mt = row >> 4;
        int mrow = row & 15;
        int qr = mrow & 7;
        int mh = mrow >> 3;
        int ks = kq >> 3;
        int kh = (kq >> 2) & 1;
        arow[h] = row;
        abase[h] = ((ks * 8 + mt) * 32 + qr * 4) * 4 + mh + 2 * kh;
    }
    int akq0 = ((t * 2) & 3) << 2;
    int akq1 = ((t * 2 + 1) & 3) << 2;
    // B: thread loads 1 float4
    int brow = t >> 4;                   // k row 0..15
    int bc4 = (t & 15) << 2;             // n 0..60
    int bbase;
    {
        int ks = brow >> 3;
        int kk = brow & 7;
        int qc = kk & 3;
        int kh = kk >> 2;
        int nt = bc4 >> 3;
        int qr0 = bc4 & 7;
        bbase = ((ks * 8 + nt) * 32 + qr0 * 4 + qc) * 2 + kh;
    }

    float acc[2][4][4];
#pragma unroll
    for (int i = 0; i < 2; i++)
#pragma unroll
        for (int j = 0; j < 4; j++)
#pragma unroll
            for (int q = 0; q < 4; q++) acc[i][j][q] = 0.0f;

    const int nk = K >> 4;   // k-tiles of 16

    float4 pa[2], pb;
    // prologue load k-tile 0
#pragma unroll
    for (int h = 0; h < 2; h++) {
        int grow = rowBase + arow[h];
        int kq = h == 0 ? akq0 : akq1;
        pa[h] = make_float4(0.f, 0.f, 0.f, 0.f);
        if (grow < M) pa[h] = *(const float4*)&A[grow * K + kq];
    }
    pb = *(const float4*)&B[brow * N + colBase + bc4];

    // store stage 0
    {
        float av[2][4] = {{pa[0].x, pa[0].y, pa[0].z, pa[0].w},
                          {pa[1].x, pa[1].y, pa[1].z, pa[1].w}};
#pragma unroll
        for (int h = 0; h < 2; h++)
#pragma unroll
            for (int j = 0; j < 4; j++) {
                float hv = to_tf32f(av[h][j]);
                AfH[0][abase[h] + j * 4] = hv;
                AfL[0][abase[h] + j * 4] = to_tf32f(av[h][j] - hv);
            }
        float bv[4] = {pb.x, pb.y, pb.z, pb.w};
#pragma unroll
        for (int j = 0; j < 4; j++) {
            float hv = to_tf32f(bv[j]);
            BfH[0][bbase + j * 8] = hv;
            BfL[0][bbase + j * 8] = to_tf32f(bv[j] - hv);
        }
    }
    __syncthreads();

    for (int it = 0; it < nk; it++) {
        // prefetch next tile
        if (it + 1 < nk) {
            int kt = (it + 1) << 4;
#pragma unroll
            for (int h = 0; h < 2; h++) {
                int grow = rowBase + arow[h];
                int kq = h == 0 ? akq0 : akq1;
                pa[h] = make_float4(0.f, 0.f, 0.f, 0.f);
                if (grow < M) pa[h] = *(const float4*)&A[grow * K + kt + kq];
            }
            pb = *(const float4*)&B[(kt + brow) * N + colBase + bc4];
        }
        // compute current stage
        int st = it & 1;
#pragma unroll
        for (int ksi = 0; ksi < 2; ksi++) {
            float4 ah[2], al[2];
#pragma unroll
            for (int i = 0; i < 2; i++) {
                int mt = warp_m * 2 + i;
                int idx = (ksi * 8 + mt) * 32 + lane;
                ah[i] = ((const float4*)AfH[st])[idx];
                al[i] = ((const float4*)AfL[st])[idx];
            }
            float2 bh[4], bl[4];
#pragma unroll
            for (int j = 0; j < 4; j++) {
                int nt = warp_n * 4 + j;
                int idx = (ksi * 8 + nt) * 32 + lane;
                bh[j] = ((const float2*)BfH[st])[idx];
                bl[j] = ((const float2*)BfL[st])[idx];
            }
#pragma unroll
            for (int i = 0; i < 2; i++)
#pragma unroll
                for (int j = 0; j < 4; j++) {
                    mma_tf32(acc[i][j], ah[i], bh[j]);
                    mma_tf32(acc[i][j], ah[i], bl[j]);
                    mma_tf32(acc[i][j], al[i], bh[j]);
                }
        }
        // store next stage
        if (it + 1 < nk) {
            int ns = (it + 1) & 1;
            float av[2][4] = {{pa[0].x, pa[0].y, pa[0].z, pa[0].w},
                              {pa[1].x, pa[1].y, pa[1].z, pa[1].w}};
#pragma unroll
            for (int h = 0; h < 2; h++)
#pragma unroll
                for (int j = 0; j < 4; j++) {
                    float hv = to_tf32f(av[h][j]);
                    AfH[ns][abase[h] + j * 4] = hv;
                    AfL[ns][abase[h] + j * 4] = to_tf32f(av[h][j] - hv);
                }
            float bv[4] = {pb.x, pb.y, pb.z, pb.w};
#pragma unroll
            for (int j = 0; j < 4; j++) {
                float hv = to_tf32f(bv[j]);
                BfH[ns][bbase + j * 8] = hv;
                BfL[ns][bbase + j * 8] = to_tf32f(bv[j] - hv);
            }
            __syncthreads();
        }
    }

    // epilogue
#pragma unroll
    for (int i = 0; i < 2; i++) {
#pragma unroll
        for (int j = 0; j < 4; j++) {
            int col0 = colBase + warp_n * 32 + j * 8 + 2 * qcol;
            float bv0 = bias[col0], bv1 = bias[col0 + 1];
#pragma unroll
            for (int h = 0; h < 2; h++) {
                int grow = rowBase + warp_m * 32 + i * 16 + qrow + h * 8;
                if (grow < M) {
                    float o0 = acc[i][j][2 * h] + bv0;
                    float o1 = acc[i][j][2 * h + 1] + bv1;
                    if (SILU) {
                        o0 = o0 / (1.0f + __expf(-o0));
                        o1 = o1 / (1.0f + __expf(-o1));
                    }
                    *(float2*)&C[grow * N + col0] = make_float2(o0, o1);
                }
            }
        }
    }
}

// ---------------- cutoff via MUFU ----------------
__device__ __forceinline__ float cw(float x) {
    float c = __cosf(x * 0.6283185307179586f);
    float w = fmaf(c, 0.5f, 0.5f);
    return (x < 5.0f) ? w : 0.0f;
}

// ---------------- main per-node kernel ----------------
__global__ void __launch_bounds__(128) k_main(const float* __restrict__ v,
                                              const float* __restrict__ Wr,
                                              const float* __restrict__ br,
                                              float* __restrict__ out) {
    __shared__ u64 sm[23][CHUNK];
    int t = threadIdx.x;

    u64 wr0d[NRBF], wr1d[NRBF], wr2d[NRBF];
#pragma unroll
    for (int k = 0; k < NRBF; k++) {
        wr0d[k] = pkdup(Wr[k * F3 + t]);
        wr1d[k] = pkdup(Wr[k * F3 + FF + t]);
        wr2d[k] = pkdup(Wr[k * F3 + 2 * FF + t]);
    }
    u64 br0d = pkdup(br[t]), br1d = pkdup(br[FF + t]), br2d = pkdup(br[2 * FF + t]);

    for (int n = blockIdx.x; n < NN; n += gridDim.x) {
        int base = g_off[n];
        int cnt = g_cnt[n];
        int npairs = (cnt + 1) >> 1;
        u64 accA = 0ull, accB = 0ull, bx = 0ull, by = 0ull, bz = 0ull;

        for (int cs = 0; cs < npairs; cs += CHUNK) {
            int nc = npairs - cs; if (nc > CHUNK) nc = CHUNK;
            __syncthreads();
            {
                int pbase = base + (cs << 1);
#pragma unroll
                for (int idx = 0; idx < 6; idx++) {
                    int q = t + idx * 128;
                    if (q < 23 * CHUNK) {
                        int j = q >> 5;
                        int i = q & 31;
                        const float* rowp;
                        if (j < NRBF)      rowp = g_rbf + j * EP + pbase;
                        else if (j == 20)  rowp = g_dirx + pbase;
                        else if (j == 21)  rowp = g_diry + pbase;
                        else               rowp = g_dirz + pbase;
                        sm[j][i] = *(const u64*)(rowp + (i << 1));
                    }
                }
            }
            __syncthreads();
            for (int i = 0; i < nc; i++) {
                u64 x0 = br0d, x1 = br1d, x2 = br2d;
#pragma unroll
                for (int k = 0; k < NRBF; k++) {
                    u64 rr = sm[k][i];
                    x0 = f2fma(rr, wr0d[k], x0);
                    x1 = f2fma(rr, wr1d[k], x1);
                    x2 = f2fma(rr, wr2d[k], x2);
                }
                float2 v0 = upk(x0), v1 = upk(x1), v2 = upk(x2);
                u64 W0 = pk2(cw(v0.x), cw(v0.y));
                u64 W1 = pk2(cw(v1.x), cw(v1.y));
                u64 W2 = pk2(cw(v2.x), cw(v2.y));
                u64 m = (((cs + i) << 1) + 1 < cnt) ? ~0ull : 0xFFFFFFFFull;
                accA = f2add(accA, W0 & m);
                accB = f2add(accB, W1 & m);
                bx = f2fma(W2, sm[20][i], bx);
                by = f2fma(W2, sm[21][i], by);
                bz = f2fma(W2, sm[22][i], bz);
            }
        }
        float2 rA = upk(accA), rB = upk(accB);
        float2 rx = upk(bx), ry = upk(by), rz = upk(bz);
        float a1 = rA.x + rA.y;
        float a2 = rB.x + rB.y;
        float cx = rx.x + rx.y;
        float cy = ry.x + ry.y;
        float cz = rz.x + rz.y;

        float ph1 = g_phi[n * F3 + t];
        float ph2 = g_phi[n * F3 + FF + t];
        float ph3 = g_phi[n * F3 + 2 * FF + t];
        int nf = n * FF + t;
        float vx = v[nf * 3 + 0], vy = v[nf * 3 + 1], vz = v[nf * 3 + 2];
        float s1v = ph1 * a1;
        out[nf * 3 + 0] = fmaf(vx, s1v, ph3 * cx);
        out[nf * 3 + 1] = fmaf(vy, s1v, ph3 * cy);
        out[nf * 3 + 2] = fmaf(vz, s1v, ph3 * cz);
        out[NN * F3 + nf] = ph2 * a2;
    }
}

// ---------------- launch ----------------
extern "C" void kernel_launch(void* const* d_in, const int* in_sizes, int n_in,
                              void* d_out, int out_size) {
    (void)in_sizes; (void)n_in; (void)out_size;
    const float* v  = (const float*)d_in[0];
    const float* s  = (const float*)d_in[1];
    const float* r  = (const float*)d_in[2];
    const float* W1 = (const float*)d_in[3];
    const float* b1 = (const float*)d_in[4];
    const float* W2 = (const float*)d_in[5];
    const float* b2 = (const float*)d_in[6];
    const float* Wr = (const float*)d_in[7];
    const float* br = (const float*)d_in[8];
    float* out = (float*)d_out;

    void* q;
    cudaGetSymbolAddress(&q, g_h);
    float* hptr = (float*)q;
    cudaGetSymbolAddress(&q, g_phi);
    float* pptr = (float*)q;

    k_init<<<(EPAD + 255) / 256, 256>>>();
    k_hist<<<(EE + 255) / 256, 256>>>(r);
    k_scan<<<1, 1024>>>();
    // gemm1 stays at launch idx 3 (ncu capture slot)
    {
        dim3 g1(FF / 64, (NN + 127) / 128);
        k_gemm_tc<true><<<g1, 256>>>(s, W1, b1, hptr, NN, FF, FF);
        dim3 g2(F3 / 64, (NN + 127) / 128);
        k_gemm_tc<false><<<g2, 256>>>(hptr, W2, b2, pptr, NN, F3, FF);
    }
    k_fill<<<(EE + 255) / 256, 256>>>(r);
    k_sortlists<<<(NN + 127) / 128, 128>>>();
    k_edge<<<(EPAD + 127) / 128, 128>>>(r);
    k_main<<<2048, 128>>>(v, Wr, br, out);
}

// round 10
// speedup vs baseline: 1.3665x; 1.3665x over previous
#include <cuda_runtime.h>
#include <cuda_bf16.h>
#include <math.h>
#include <stdint.h>

#define NN 50000
#define EE 400000
#define FF 128
#define F3 384
#define NRBF 20
#define EPAD (EE + NN)
#define EP 450560
#define CHUNK 32
#define NTILE 391                 // ceil(50000/128)
#define ROWS_PAD (NTILE * 128)    // 50048
#define SMEM_U32 26112            // 2*(128*68) + 2*(64*68)
#define SMEM_B (SMEM_U32 * 4)     // 104448 bytes

typedef unsigned long long u64;

// ---------------- f32x2 packed helpers ----------------
__device__ __forceinline__ u64 pk2(float a, float b) {
    u64 r; asm("mov.b64 %0,{%1,%2};" : "=l"(r) : "f"(a), "f"(b)); return r;
}
__device__ __forceinline__ u64 pkdup(float a) {
    u64 r; asm("mov.b64 %0,{%1,%1};" : "=l"(r) : "f"(a)); return r;
}
__device__ __forceinline__ float2 upk(u64 v) {
    float2 f; asm("mov.b64 {%0,%1},%2;" : "=f"(f.x), "=f"(f.y) : "l"(v)); return f;
}
__device__ __forceinline__ u64 f2fma(u64 a, u64 b, u64 c) {
    u64 d; asm("fma.rn.f32x2 %0,%1,%2,%3;" : "=l"(d) : "l"(a), "l"(b), "l"(c)); return d;
}
__device__ __forceinline__ u64 f2add(u64 a, u64 b) {
    u64 d; asm("add.rn.f32x2 %0,%1,%2;" : "=l"(d) : "l"(a), "l"(b)); return d;
}

// ---------------- bf16 helpers ----------------
__device__ __forceinline__ uint32_t pack_bf2(__nv_bfloat16 lo, __nv_bfloat16 hi) {
    return ((uint32_t)__bfloat16_as_ushort(hi) << 16) | (uint32_t)__bfloat16_as_ushort(lo);
}
__device__ __forceinline__ void split2_pack(float v0, float v1, uint32_t& uh, uint32_t& ul) {
    __nv_bfloat16 h0 = __float2bfloat16(v0);
    __nv_bfloat16 h1 = __float2bfloat16(v1);
    __nv_bfloat16 l0 = __float2bfloat16(v0 - __bfloat162float(h0));
    __nv_bfloat16 l1 = __float2bfloat16(v1 - __bfloat162float(h1));
    uh = pack_bf2(h0, h1);
    ul = pack_bf2(l0, l1);
}
__device__ __forceinline__ void mma_bf16(float c[4], const uint32_t a[4],
                                         uint32_t b0, uint32_t b1) {
    asm volatile("mma.sync.aligned.m16n8k16.row.col.f32.bf16.bf16.f32 "
                 "{%0,%1,%2,%3},{%4,%5,%6,%7},{%8,%9},{%0,%1,%2,%3};"
                 : "+f"(c[0]), "+f"(c[1]), "+f"(c[2]), "+f"(c[3])
                 : "r"(a[0]), "r"(a[1]), "r"(a[2]), "r"(a[3]), "r"(b0), "r"(b1));
}

// ---------------- scratch ----------------
__device__ float g_phi[NN * F3];
__device__ float g_rbf[NRBF * EP];
__device__ float g_dirx[EP];
__device__ float g_diry[EP];
__device__ float g_dirz[EP];
__device__ int   g_cnt[NN];
__device__ int   g_off[NN];
__device__ int   g_cur[NN];
__device__ int   g_order[EPAD];
// pair-packed bf16 hi/lo operands ([row][64] u32, k-adjacent pairs)
__device__ uint32_t g_s2H[ROWS_PAD * 64];
__device__ uint32_t g_s2L[ROWS_PAD * 64];
__device__ uint32_t g_h2H[ROWS_PAD * 64];
__device__ uint32_t g_h2L[ROWS_PAD * 64];
__device__ uint32_t g_w1H2[FF * 64];
__device__ uint32_t g_w1L2[FF * 64];
__device__ uint32_t g_w2H2[F3 * 64];
__device__ uint32_t g_w2L2[F3 * 64];

// ---------------- prep: weights -> W^T pair-packed bf16 hi/lo ----------------
__global__ void k_prepW(const float* __restrict__ W1, const float* __restrict__ W2) {
    int idx = blockIdx.x * blockDim.x + threadIdx.x;
    if (idx < FF * 64) {
        int n = idx >> 6, p = idx & 63;
        float v0 = W1[(2 * p) * FF + n];
        float v1 = W1[(2 * p + 1) * FF + n];
        uint32_t uh, ul; split2_pack(v0, v1, uh, ul);
        g_w1H2[idx] = uh; g_w1L2[idx] = ul;
    } else if (idx < (FF + F3) * 64) {
        int r = idx - FF * 64;
        int n = r >> 6, p = r & 63;
        float v0 = W2[(2 * p) * F3 + n];
        float v1 = W2[(2 * p + 1) * F3 + n];
        uint32_t uh, ul; split2_pack(v0, v1, uh, ul);
        g_w2H2[r] = uh; g_w2L2[r] = ul;
    }
}

// ---------------- prep: s -> pair-packed bf16 hi/lo (padded rows = 0) ----------------
__global__ void k_prepS(const float* __restrict__ s) {
    int idx = blockIdx.x * blockDim.x + threadIdx.x;
    if (idx >= ROWS_PAD * 64) return;
    int row = idx >> 6, p = idx & 63;
    float v0 = 0.f, v1 = 0.f;
    if (row < NN) {
        float2 q = *(const float2*)&s[row * FF + 2 * p];
        v0 = q.x; v1 = q.y;
    }
    uint32_t uh, ul; split2_pack(v0, v1, uh, ul);
    g_s2H[idx] = uh; g_s2L[idx] = ul;
}

// ---------------- 3xBF16 mma.sync GEMM, whole-K staged once ----------------
// BM=128, BN=64, K=128. 256 thr = 8 warps (4m x 2n), warp tile 32x32.
template <bool SILU, bool OUTBF16>
__global__ void __launch_bounds__(256) k_gemm_bf(const uint32_t* __restrict__ A2H,
                                                 const uint32_t* __restrict__ A2L,
                                                 const uint32_t* __restrict__ B2H,
                                                 const uint32_t* __restrict__ B2L,
                                                 const float* __restrict__ bias,
                                                 uint32_t* __restrict__ OH,
                                                 uint32_t* __restrict__ OL,
                                                 float* __restrict__ PHI,
                                                 int outN, int M) {
    extern __shared__ __align__(16) uint32_t smem[];
    uint32_t* sAh = smem;               // 128*68
    uint32_t* sAl = smem + 8704;
    uint32_t* sBh = smem + 17408;       // 64*68
    uint32_t* sBl = smem + 21760;

    int t = threadIdx.x;
    int lane = t & 31, wid = t >> 5;
    int warp_m = wid >> 1, warp_n = wid & 1;
    int lr = lane >> 2, lc = lane & 3;
    int rowBase = blockIdx.y * 128;
    int colBase = blockIdx.x * 64;

    // stage A (128 rows x 16 uint4) hi+lo
    {
        const uint4* gh = (const uint4*)(A2H + (size_t)rowBase * 64);
        const uint4* gl = (const uint4*)(A2L + (size_t)rowBase * 64);
#pragma unroll
        for (int sl = t; sl < 2048; sl += 256) {
            int row = sl >> 4, q = sl & 15;
            ((uint4*)(sAh + row * 68))[q] = gh[sl];
            ((uint4*)(sAl + row * 68))[q] = gl[sl];
        }
        const uint4* bh_ = (const uint4*)(B2H + (size_t)colBase * 64);
        const uint4* bl_ = (const uint4*)(B2L + (size_t)colBase * 64);
#pragma unroll
        for (int sl = t; sl < 1024; sl += 256) {
            int row = sl >> 4, q = sl & 15;
            ((uint4*)(sBh + row * 68))[q] = bh_[sl];
            ((uint4*)(sBl + row * 68))[q] = bl_[sl];
        }
    }
    __syncthreads();

    float acc[2][4][4];
#pragma unroll
    for (int i = 0; i < 2; i++)
#pragma unroll
        for (int j = 0; j < 4; j++)
#pragma unroll
            for (int q = 0; q < 4; q++) acc[i][j][q] = 0.0f;

#pragma unroll
    for (int ks = 0; ks < 8; ks++) {
        int c2 = lc + ks * 8;
        uint32_t ah[2][4], al[2][4];
#pragma unroll
        for (int i = 0; i < 2; i++) {
            int r0 = warp_m * 32 + i * 16 + lr;
            int b0 = r0 * 68;
            ah[i][0] = sAh[b0 + c2];
            ah[i][1] = sAh[b0 + 8 * 68 + c2];
            ah[i][2] = sAh[b0 + c2 + 4];
            ah[i][3] = sAh[b0 + 8 * 68 + c2 + 4];
            al[i][0] = sAl[b0 + c2];
            al[i][1] = sAl[b0 + 8 * 68 + c2];
            al[i][2] = sAl[b0 + c2 + 4];
            al[i][3] = sAl[b0 + 8 * 68 + c2 + 4];
        }
        uint32_t bh[4][2], bl[4][2];
#pragma unroll
        for (int j = 0; j < 4; j++) {
            int n0 = warp_n * 32 + j * 8 + lr;
            int bb = n0 * 68;
            bh[j][0] = sBh[bb + c2];
            bh[j][1] = sBh[bb + c2 + 4];
            bl[j][0] = sBl[bb + c2];
            bl[j][1] = sBl[bb + c2 + 4];
        }
#pragma unroll
        for (int i = 0; i < 2; i++)
#pragma unroll
            for (int j = 0; j < 4; j++) {
                mma_bf16(acc[i][j], ah[i], bh[j][0], bh[j][1]);
                mma_bf16(acc[i][j], ah[i], bl[j][0], bl[j][1]);
                mma_bf16(acc[i][j], al[i], bh[j][0], bh[j][1]);
            }
    }

    // epilogue
#pragma unroll
    for (int i = 0; i < 2; i++) {
#pragma unroll
        for (int j = 0; j < 4; j++) {
            int col0 = warp_n * 32 + j * 8 + lc * 2;
            int gcol = colBase + col0;
            float b0 = bias[gcol], b1 = bias[gcol + 1];
#pragma unroll
            for (int h = 0; h < 2; h++) {
                int grow = rowBase + warp_m * 32 + i * 16 + lr + h * 8;
                float v0 = acc[i][j][2 * h] + b0;
                float v1 = acc[i][j][2 * h + 1] + b1;
                if (SILU) {
                    v0 = v0 / (1.0f + __expf(-v0));
                    v1 = v1 / (1.0f + __expf(-v1));
                }
                if (OUTBF16) {
                    uint32_t uh, ul; split2_pack(v0, v1, uh, ul);
                    int oi = grow * 64 + (gcol >> 1);
                    OH[oi] = uh; OL[oi] = ul;
                } else {
                    if (grow < M)
                        *(float2*)&PHI[(size_t)grow * outN + gcol] = make_float2(v0, v1);
                }
            }
        }
    }
}

// ---------------- CSR build ----------------
__global__ void k_init() {
    int i = blockIdx.x * blockDim.x + threadIdx.x;
    if (i < NN) g_cnt[i] = 0;
    if (i < EPAD) g_order[i] = -1;
}

__global__ void k_hist(const float* __restrict__ r) {
    int e = blockIdx.x * blockDim.x + threadIdx.x;
    if (e < EE) {
        int jn = (int)r[e * 5 + 1];
        atomicAdd(&g_cnt[jn], 1);
    }
}

__global__ void k_scan() {
    __shared__ int part[1024];
    int t = threadIdx.x;
    const int CH = (NN + 1023) / 1024;
    int base = t * CH, sum = 0;
    for (int i = 0; i < CH; i++) {
        int idx = base + i;
        if (idx < NN) sum += (g_cnt[idx] + 1) & ~1;
    }
    part[t] = sum;
    __syncthreads();
    for (int off = 1; off < 1024; off <<= 1) {
        int v = (t >= off) ? part[t - off] : 0;
        __syncthreads();
        part[t] += v;
        __syncthreads();
    }
    int run = (t > 0) ? part[t - 1] : 0;
    for (int i = 0; i < CH; i++) {
        int idx = base + i;
        if (idx < NN) {
            g_off[idx] = run;
            g_cur[idx] = run;
            run += (g_cnt[idx] + 1) & ~1;
        }
    }
}

__global__ void k_fill(const float* __restrict__ r) {
    int e = blockIdx.x * blockDim.x + threadIdx.x;
    if (e < EE) {
        int jn = (int)r[e * 5 + 1];
        int pos = atomicAdd(&g_cur[jn], 1);
        g_order[pos] = e;
    }
}

__global__ void k_sortlists() {
    int n = blockIdx.x * blockDim.x + threadIdx.x;
    if (n >= NN) return;
    int s0 = g_off[n], s1 = s0 + g_cnt[n];
    for (int i = s0 + 1; i < s1; i++) {
        int key = g_order[i];
        int jj = i - 1;
        while (jj >= s0 && g_order[jj] > key) {
            g_order[jj + 1] = g_order[jj];
            jj--;
        }
        g_order[jj + 1] = key;
    }
}

// ---------------- per-edge precompute ----------------
__global__ void k_edge(const float* __restrict__ r) {
    int p = blockIdx.x * blockDim.x + threadIdx.x;
    if (p >= EPAD) return;
    int eid = g_order[p];
    if (eid < 0) {
#pragma unroll
        for (int k = 0; k < NRBF; k++) g_rbf[k * EP + p] = 0.0f;
        g_dirx[p] = 0.0f; g_diry[p] = 0.0f; g_dirz[p] = 0.0f;
        return;
    }
    float rx = r[eid * 5 + 2];
    float ry = r[eid * 5 + 3];
    float rz = r[eid * 5 + 4];
    float z = fabsf(rz);
    float inv = 1.0f / (z + 1e-8f);
    float th = 0.6283185307179586f * z;
    float s, c;
    sincosf(th, &s, &c);
    float twoc = 2.0f * c;
    float skm = 0.0f, sk = s;
#pragma unroll
    for (int k = 0; k < NRBF; k++) {
        g_rbf[k * EP + p] = sk * inv;
        float nxt = fmaf(twoc, sk, -skm);
        skm = sk; sk = nxt;
    }
    float nrm = sqrtf(rx * rx + ry * ry + rz * rz);
    float invn = 1.0f / (nrm + 1e-8f);
    g_dirx[p] = rx * invn;
    g_diry[p] = ry * invn;
    g_dirz[p] = rz * invn;
}

// ---------------- cutoff via MUFU ----------------
__device__ __forceinline__ float cw(float x) {
    float c = __cosf(x * 0.6283185307179586f);
    float w = fmaf(c, 0.5f, 0.5f);
    return (x < 5.0f) ? w : 0.0f;
}

// ---------------- main per-node kernel ----------------
__global__ void __launch_bounds__(128) k_main(const float* __restrict__ v,
                                              const float* __restrict__ Wr,
                                              const float* __restrict__ br,
                                              float* __restrict__ out) {
    __shared__ u64 sm[23][CHUNK];
    int t = threadIdx.x;

    u64 wr0d[NRBF], wr1d[NRBF], wr2d[NRBF];
#pragma unroll
    for (int k = 0; k < NRBF; k++) {
        wr0d[k] = pkdup(Wr[k * F3 + t]);
        wr1d[k] = pkdup(Wr[k * F3 + FF + t]);
        wr2d[k] = pkdup(Wr[k * F3 + 2 * FF + t]);
    }
    u64 br0d = pkdup(br[t]), br1d = pkdup(br[FF + t]), br2d = pkdup(br[2 * FF + t]);

    for (int n = blockIdx.x; n < NN; n += gridDim.x) {
        int base = g_off[n];
        int cnt = g_cnt[n];
        int npairs = (cnt + 1) >> 1;
        u64 accA = 0ull, accB = 0ull, bx = 0ull, by = 0ull, bz = 0ull;

        for (int cs = 0; cs < npairs; cs += CHUNK) {
            int nc = npairs - cs; if (nc > CHUNK) nc = CHUNK;
            __syncthreads();
            {
                int pbase = base + (cs << 1);
#pragma unroll
                for (int idx = 0; idx < 6; idx++) {
                    int q = t + idx * 128;
                    if (q < 23 * CHUNK) {
                        int jr = q >> 5;
                        int i = q & 31;
                        const float* rowp;
                        if (jr < NRBF)      rowp = g_rbf + jr * EP + pbase;
                        else if (jr == 20)  rowp = g_dirx + pbase;
                        else if (jr == 21)  rowp = g_diry + pbase;
                        else                rowp = g_dirz + pbase;
                        sm[jr][i] = *(const u64*)(rowp + (i << 1));
                    }
                }
            }
            __syncthreads();
            for (int i = 0; i < nc; i++) {
                u64 x0 = br0d, x1 = br1d, x2 = br2d;
#pragma unroll
                for (int k = 0; k < NRBF; k++) {
                    u64 rr = sm[k][i];
                    x0 = f2fma(rr, wr0d[k], x0);
                    x1 = f2fma(rr, wr1d[k], x1);
                    x2 = f2fma(rr, wr2d[k], x2);
                }
                float2 v0 = upk(x0), v1 = upk(x1), v2 = upk(x2);
                u64 W0 = pk2(cw(v0.x), cw(v0.y));
                u64 W1v = pk2(cw(v1.x), cw(v1.y));
                u64 W2v = pk2(cw(v2.x), cw(v2.y));
                u64 m = (((cs + i) << 1) + 1 < cnt) ? ~0ull : 0xFFFFFFFFull;
                accA = f2add(accA, W0 & m);
                accB = f2add(accB, W1v & m);
                bx = f2fma(W2v, sm[20][i], bx);
                by = f2fma(W2v, sm[21][i], by);
                bz = f2fma(W2v, sm[22][i], bz);
            }
        }
        float2 rA = upk(accA), rB = upk(accB);
        float2 rx = upk(bx), ry = upk(by), rz = upk(bz);
        float a1 = rA.x + rA.y;
        float a2 = rB.x + rB.y;
        float cx = rx.x + rx.y;
        float cy = ry.x + ry.y;
        float cz = rz.x + rz.y;

        float ph1 = g_phi[n * F3 + t];
        float ph2 = g_phi[n * F3 + FF + t];
        float ph3 = g_phi[n * F3 + 2 * FF + t];
        int nf = n * FF + t;
        float vx = v[nf * 3 + 0], vy = v[nf * 3 + 1], vz = v[nf * 3 + 2];
        float s1v = ph1 * a1;
        out[nf * 3 + 0] = fmaf(vx, s1v, ph3 * cx);
        out[nf * 3 + 1] = fmaf(vy, s1v, ph3 * cy);
        out[nf * 3 + 2] = fmaf(vz, s1v, ph3 * cz);
        out[NN * F3 + nf] = ph2 * a2;
    }
}

// ---------------- launch ----------------
extern "C" void kernel_launch(void* const* d_in, const int* in_sizes, int n_in,
                              void* d_out, int out_size) {
    (void)in_sizes; (void)n_in; (void)out_size;
    const float* v  = (const float*)d_in[0];
    const float* s  = (const float*)d_in[1];
    const float* r  = (const float*)d_in[2];
    const float* W1 = (const float*)d_in[3];
    const float* b1 = (const float*)d_in[4];
    const float* W2 = (const float*)d_in[5];
    const float* b2 = (const float*)d_in[6];
    const float* Wr = (const float*)d_in[7];
    const float* br = (const float*)d_in[8];
    float* out = (float*)d_out;

    cudaFuncSetAttribute(k_gemm_bf<true, true>,
                         cudaFuncAttributeMaxDynamicSharedMemorySize, SMEM_B);
    cudaFuncSetAttribute(k_gemm_bf<false, false>,
                         cudaFuncAttributeMaxDynamicSharedMemorySize, SMEM_B);

    void* q;
    uint32_t *sH, *sL, *hH, *hL, *w1H, *w1L, *w2H, *w2L;
    float* pphi;
    cudaGetSymbolAddress(&q, g_s2H);  sH  = (uint32_t*)q;
    cudaGetSymbolAddress(&q, g_s2L);  sL  = (uint32_t*)q;
    cudaGetSymbolAddress(&q, g_h2H);  hH  = (uint32_t*)q;
    cudaGetSymbolAddress(&q, g_h2L);  hL  = (uint32_t*)q;
    cudaGetSymbolAddress(&q, g_w1H2); w1H = (uint32_t*)q;
    cudaGetSymbolAddress(&q, g_w1L2); w1L = (uint32_t*)q;
    cudaGetSymbolAddress(&q, g_w2H2); w2H = (uint32_t*)q;
    cudaGetSymbolAddress(&q, g_w2L2); w2L = (uint32_t*)q;
    cudaGetSymbolAddress(&q, g_phi);  pphi = (float*)q;

    k_prepW<<<((FF + F3) * 64 + 255) / 256, 256>>>(W1, W2);
    k_prepS<<<(ROWS_PAD * 64 + 255) / 256, 256>>>(s);
    k_init<<<(EPAD + 255) / 256, 256>>>();
    // launch #4 = gemm1 (ncu capture slot)
    k_gemm_bf<true, true><<<dim3(2, NTILE), 256, SMEM_B>>>(
        sH, sL, w1H, w1L, b1, hH, hL, nullptr, 0, NN);
    k_gemm_bf<false, false><<<dim3(6, NTILE), 256, SMEM_B>>>(
        hH, hL, w2H, w2L, b2, nullptr, nullptr, pphi, F3, NN);
    k_hist<<<(EE + 255) / 256, 256>>>(r);
    k_scan<<<1, 1024>>>();
    k_fill<<<(EE + 255) / 256, 256>>>(r);
    k_sortlists<<<(NN + 127) / 128, 128>>>();
    k_edge<<<(EPAD + 127) / 128, 128>>>(r);
    k_main<<<2048, 128>>>(v, Wr, br, out);
}

// round 11
// speedup vs baseline: 1.3961x; 1.0217x over previous
#include <cuda_runtime.h>
#include <cuda_bf16.h>
#include <math.h>
#include <stdint.h>

#define NN 50000
#define EE 400000
#define FF 128
#define F3 384
#define NRBF 20
#define EPAD (EE + NN)
#define EP 450560
#define NTILE 391                 // ceil(50000/128)
#define ROWS_PAD (NTILE * 128)    // 50048
#define SMEM_U32 26112            // 2*(128*68) + 2*(64*68)
#define SMEM_B (SMEM_U32 * 4)     // 104448 bytes

typedef unsigned long long u64;

// ---------------- f32x2 packed helpers ----------------
__device__ __forceinline__ u64 pk2(float a, float b) {
    u64 r; asm("mov.b64 %0,{%1,%2};" : "=l"(r) : "f"(a), "f"(b)); return r;
}
__device__ __forceinline__ u64 pkdup(float a) {
    u64 r; asm("mov.b64 %0,{%1,%1};" : "=l"(r) : "f"(a)); return r;
}
__device__ __forceinline__ float2 upk(u64 v) {
    float2 f; asm("mov.b64 {%0,%1},%2;" : "=f"(f.x), "=f"(f.y) : "l"(v)); return f;
}
__device__ __forceinline__ u64 f2fma(u64 a, u64 b, u64 c) {
    u64 d; asm("fma.rn.f32x2 %0,%1,%2,%3;" : "=l"(d) : "l"(a), "l"(b), "l"(c)); return d;
}
__device__ __forceinline__ u64 f2add(u64 a, u64 b) {
    u64 d; asm("add.rn.f32x2 %0,%1,%2;" : "=l"(d) : "l"(a), "l"(b)); return d;
}

// ---------------- bf16 helpers ----------------
__device__ __forceinline__ uint32_t pack_bf2(__nv_bfloat16 lo, __nv_bfloat16 hi) {
    return ((uint32_t)__bfloat16_as_ushort(hi) << 16) | (uint32_t)__bfloat16_as_ushort(lo);
}
__device__ __forceinline__ void split2_pack(float v0, float v1, uint32_t& uh, uint32_t& ul) {
    __nv_bfloat16 h0 = __float2bfloat16(v0);
    __nv_bfloat16 h1 = __float2bfloat16(v1);
    __nv_bfloat16 l0 = __float2bfloat16(v0 - __bfloat162float(h0));
    __nv_bfloat16 l1 = __float2bfloat16(v1 - __bfloat162float(h1));
    uh = pack_bf2(h0, h1);
    ul = pack_bf2(l0, l1);
}
__device__ __forceinline__ void mma_bf16(float c[4], const uint32_t a[4],
                                         uint32_t b0, uint32_t b1) {
    asm volatile("mma.sync.aligned.m16n8k16.row.col.f32.bf16.bf16.f32 "
                 "{%0,%1,%2,%3},{%4,%5,%6,%7},{%8,%9},{%0,%1,%2,%3};"
                 : "+f"(c[0]), "+f"(c[1]), "+f"(c[2]), "+f"(c[3])
                 : "r"(a[0]), "r"(a[1]), "r"(a[2]), "r"(a[3]), "r"(b0), "r"(b1));
}

// ---------------- scratch ----------------
__device__ float g_phi[NN * F3];
__device__ float g_rbf[NRBF * EP];
__device__ float g_dirx[EP];
__device__ float g_diry[EP];
__device__ float g_dirz[EP];
__device__ int   g_cnt[NN];
__device__ int   g_off[NN];
__device__ int   g_cur[NN];
__device__ int   g_order[EPAD];
__device__ uint32_t g_s2H[ROWS_PAD * 64];
__device__ uint32_t g_s2L[ROWS_PAD * 64];
__device__ uint32_t g_h2H[ROWS_PAD * 64];
__device__ uint32_t g_h2L[ROWS_PAD * 64];
__device__ uint32_t g_w1H2[FF * 64];
__device__ uint32_t g_w1L2[FF * 64];
__device__ uint32_t g_w2H2[F3 * 64];
__device__ uint32_t g_w2L2[F3 * 64];

// ---------------- prep: weights -> W^T pair-packed bf16 hi/lo ----------------
__global__ void k_prepW(const float* __restrict__ W1, const float* __restrict__ W2) {
    int idx = blockIdx.x * blockDim.x + threadIdx.x;
    if (idx < FF * 64) {
        int n = idx >> 6, p = idx & 63;
        float v0 = W1[(2 * p) * FF + n];
        float v1 = W1[(2 * p + 1) * FF + n];
        uint32_t uh, ul; split2_pack(v0, v1, uh, ul);
        g_w1H2[idx] = uh; g_w1L2[idx] = ul;
    } else if (idx < (FF + F3) * 64) {
        int r = idx - FF * 64;
        int n = r >> 6, p = r & 63;
        float v0 = W2[(2 * p) * F3 + n];
        float v1 = W2[(2 * p + 1) * F3 + n];
        uint32_t uh, ul; split2_pack(v0, v1, uh, ul);
        g_w2H2[r] = uh; g_w2L2[r] = ul;
    }
}

// ---------------- prep: s -> pair-packed bf16 hi/lo (padded rows = 0) ----------------
__global__ void k_prepS(const float* __restrict__ s) {
    int idx = blockIdx.x * blockDim.x + threadIdx.x;
    if (idx >= ROWS_PAD * 64) return;
    int row = idx >> 6, p = idx & 63;
    float v0 = 0.f, v1 = 0.f;
    if (row < NN) {
        float2 q = *(const float2*)&s[row * FF + 2 * p];
        v0 = q.x; v1 = q.y;
    }
    uint32_t uh, ul; split2_pack(v0, v1, uh, ul);
    g_s2H[idx] = uh; g_s2L[idx] = ul;
}

// ---------------- 3xBF16 mma.sync GEMM, whole-K staged once, NJ col blocks ----------------
// BM=128, BN=64 per block-col, K=128. 256 thr = 8 warps (4m x 2n), warp tile 32x32.
template <bool SILU, bool OUTBF16, int NJ>
__global__ void __launch_bounds__(256) k_gemm_bf(const uint32_t* __restrict__ A2H,
                                                 const uint32_t* __restrict__ A2L,
                                                 const uint32_t* __restrict__ B2H,
                                                 const uint32_t* __restrict__ B2L,
                                                 const float* __restrict__ bias,
                                                 uint32_t* __restrict__ OH,
                                                 uint32_t* __restrict__ OL,
                                                 float* __restrict__ PHI,
                                                 int outN, int M) {
    extern __shared__ __align__(16) uint32_t smem[];
    uint32_t* sAh = smem;               // 128*68
    uint32_t* sAl = smem + 8704;
    uint32_t* sBh = smem + 17408;       // 64*68
    uint32_t* sBl = smem + 21760;

    int t = threadIdx.x;
    int lane = t & 31, wid = t >> 5;
    int warp_m = wid >> 1, warp_n = wid & 1;
    int lr = lane >> 2, lc = lane & 3;
    int rowBase = blockIdx.y * 128;

    // stage A once (128 rows x 16 uint4) hi+lo
    {
        const uint4* gh = (const uint4*)(A2H + (size_t)rowBase * 64);
        const uint4* gl = (const uint4*)(A2L + (size_t)rowBase * 64);
#pragma unroll
        for (int sl = t; sl < 2048; sl += 256) {
            int row = sl >> 4, q = sl & 15;
            ((uint4*)(sAh + row * 68))[q] = gh[sl];
            ((uint4*)(sAl + row * 68))[q] = gl[sl];
        }
    }

#pragma unroll
    for (int jc = 0; jc < NJ; jc++) {
        int colBase = (blockIdx.x * NJ + jc) * 64;
        // stage B for this column block
        {
            const uint4* bh_ = (const uint4*)(B2H + (size_t)colBase * 64);
            const uint4* bl_ = (const uint4*)(B2L + (size_t)colBase * 64);
#pragma unroll
            for (int sl = t; sl < 1024; sl += 256) {
                int row = sl >> 4, q = sl & 15;
                ((uint4*)(sBh + row * 68))[q] = bh_[sl];
                ((uint4*)(sBl + row * 68))[q] = bl_[sl];
            }
        }
        __syncthreads();

        float acc[2][4][4];
#pragma unroll
        for (int i = 0; i < 2; i++)
#pragma unroll
            for (int j = 0; j < 4; j++)
#pragma unroll
                for (int q = 0; q < 4; q++) acc[i][j][q] = 0.0f;

#pragma unroll
        for (int ks = 0; ks < 8; ks++) {
            int c2 = lc + ks * 8;
            uint32_t ah[2][4], al[2][4];
#pragma unroll
            for (int i = 0; i < 2; i++) {
                int r0 = warp_m * 32 + i * 16 + lr;
                int b0 = r0 * 68;
                ah[i][0] = sAh[b0 + c2];
                ah[i][1] = sAh[b0 + 8 * 68 + c2];
                ah[i][2] = sAh[b0 + c2 + 4];
                ah[i][3] = sAh[b0 + 8 * 68 + c2 + 4];
                al[i][0] = sAl[b0 + c2];
                al[i][1] = sAl[b0 + 8 * 68 + c2];
                al[i][2] = sAl[b0 + c2 + 4];
                al[i][3] = sAl[b0 + 8 * 68 + c2 + 4];
            }
            uint32_t bh[4][2], bl[4][2];
#pragma unroll
            for (int j = 0; j < 4; j++) {
                int n0 = warp_n * 32 + j * 8 + lr;
                int bb = n0 * 68;
                bh[j][0] = sBh[bb + c2];
                bh[j][1] = sBh[bb + c2 + 4];
                bl[j][0] = sBl[bb + c2];
                bl[j][1] = sBl[bb + c2 + 4];
            }
#pragma unroll
            for (int i = 0; i < 2; i++)
#pragma unroll
                for (int j = 0; j < 4; j++) {
                    mma_bf16(acc[i][j], ah[i], bh[j][0], bh[j][1]);
                    mma_bf16(acc[i][j], ah[i], bl[j][0], bl[j][1]);
                    mma_bf16(acc[i][j], al[i], bh[j][0], bh[j][1]);
                }
        }

        // epilogue
#pragma unroll
        for (int i = 0; i < 2; i++) {
#pragma unroll
            for (int j = 0; j < 4; j++) {
                int col0 = warp_n * 32 + j * 8 + lc * 2;
                int gcol = colBase + col0;
                float b0 = bias[gcol], b1 = bias[gcol + 1];
#pragma unroll
                for (int h = 0; h < 2; h++) {
                    int grow = rowBase + warp_m * 32 + i * 16 + lr + h * 8;
                    float v0 = acc[i][j][2 * h] + b0;
                    float v1 = acc[i][j][2 * h + 1] + b1;
                    if (SILU) {
                        v0 = v0 / (1.0f + __expf(-v0));
                        v1 = v1 / (1.0f + __expf(-v1));
                    }
                    if (OUTBF16) {
                        uint32_t uh, ul; split2_pack(v0, v1, uh, ul);
                        int oi = grow * 64 + (gcol >> 1);
                        OH[oi] = uh; OL[oi] = ul;
                    } else {
                        if (grow < M)
                            *(float2*)&PHI[(size_t)grow * outN + gcol] = make_float2(v0, v1);
                    }
                }
            }
        }
        __syncthreads();
    }
}

// ---------------- CSR build ----------------
__global__ void k_init() {
    int i = blockIdx.x * blockDim.x + threadIdx.x;
    if (i < NN) g_cnt[i] = 0;
    if (i < EPAD) g_order[i] = -1;
}

__global__ void k_hist(const float* __restrict__ r) {
    int e = blockIdx.x * blockDim.x + threadIdx.x;
    if (e < EE) {
        int jn = (int)r[e * 5 + 1];
        atomicAdd(&g_cnt[jn], 1);
    }
}

__global__ void k_scan() {
    __shared__ int part[1024];
    int t = threadIdx.x;
    const int CH = (NN + 1023) / 1024;
    int base = t * CH, sum = 0;
    for (int i = 0; i < CH; i++) {
        int idx = base + i;
        if (idx < NN) sum += (g_cnt[idx] + 1) & ~1;
    }
    part[t] = sum;
    __syncthreads();
    for (int off = 1; off < 1024; off <<= 1) {
        int v = (t >= off) ? part[t - off] : 0;
        __syncthreads();
        part[t] += v;
        __syncthreads();
    }
    int run = (t > 0) ? part[t - 1] : 0;
    for (int i = 0; i < CH; i++) {
        int idx = base + i;
        if (idx < NN) {
            g_off[idx] = run;
            g_cur[idx] = run;
            run += (g_cnt[idx] + 1) & ~1;
        }
    }
}

__global__ void k_fill(const float* __restrict__ r) {
    int e = blockIdx.x * blockDim.x + threadIdx.x;
    if (e < EE) {
        int jn = (int)r[e * 5 + 1];
        int pos = atomicAdd(&g_cur[jn], 1);
        g_order[pos] = e;
    }
}

__global__ void k_sortlists() {
    int n = blockIdx.x * blockDim.x + threadIdx.x;
    if (n >= NN) return;
    int s0 = g_off[n], s1 = s0 + g_cnt[n];
    for (int i = s0 + 1; i < s1; i++) {
        int key = g_order[i];
        int jj = i - 1;
        while (jj >= s0 && g_order[jj] > key) {
            g_order[jj + 1] = g_order[jj];
            jj--;
        }
        g_order[jj + 1] = key;
    }
}

// ---------------- per-edge precompute ----------------
__global__ void k_edge(const float* __restrict__ r) {
    int p = blockIdx.x * blockDim.x + threadIdx.x;
    if (p >= EPAD) return;
    int eid = g_order[p];
    if (eid < 0) {
#pragma unroll
        for (int k = 0; k < NRBF; k++) g_rbf[k * EP + p] = 0.0f;
        g_dirx[p] = 0.0f; g_diry[p] = 0.0f; g_dirz[p] = 0.0f;
        return;
    }
    float rx = r[eid * 5 + 2];
    float ry = r[eid * 5 + 3];
    float rz = r[eid * 5 + 4];
    float z = fabsf(rz);
    float inv = 1.0f / (z + 1e-8f);
    float th = 0.6283185307179586f * z;
    float s, c;
    sincosf(th, &s, &c);
    float twoc = 2.0f * c;
    float skm = 0.0f, sk = s;
#pragma unroll
    for (int k = 0; k < NRBF; k++) {
        g_rbf[k * EP + p] = sk * inv;
        float nxt = fmaf(twoc, sk, -skm);
        skm = sk; sk = nxt;
    }
    float nrm = sqrtf(rx * rx + ry * ry + rz * rz);
    float invn = 1.0f / (nrm + 1e-8f);
    g_dirx[p] = rx * invn;
    g_diry[p] = ry * invn;
    g_dirz[p] = rz * invn;
}

// ---------------- cutoff via MUFU ----------------
__device__ __forceinline__ float cw(float x) {
    float c = __cosf(x * 0.6283185307179586f);
    float w = fmaf(c, 0.5f, 0.5f);
    return (x < 5.0f) ? w : 0.0f;
}

// ---------------- main per-node kernel: 8-pair chunks, double-buffered 1-sync ----------------
__global__ void __launch_bounds__(128) k_main(const float* __restrict__ v,
                                              const float* __restrict__ Wr,
                                              const float* __restrict__ br,
                                              float* __restrict__ out) {
    __shared__ u64 sm[2][23][8];
    int t = threadIdx.x;

    u64 wr0d[NRBF], wr1d[NRBF], wr2d[NRBF];
#pragma unroll
    for (int k = 0; k < NRBF; k++) {
        wr0d[k] = pkdup(Wr[k * F3 + t]);
        wr1d[k] = pkdup(Wr[k * F3 + FF + t]);
        wr2d[k] = pkdup(Wr[k * F3 + 2 * FF + t]);
    }
    u64 br0d = pkdup(br[t]), br1d = pkdup(br[FF + t]), br2d = pkdup(br[2 * FF + t]);

    int cc = 0;   // running chunk counter: buffer parity continuous across nodes
    for (int n = blockIdx.x; n < NN; n += gridDim.x) {
        int base = g_off[n];
        int cnt = g_cnt[n];
        int npairs = (cnt + 1) >> 1;
        int nchunks = (npairs + 7) >> 3;
        u64 accA = 0ull, accB = 0ull, bx = 0ull, by = 0ull, bz = 0ull;

        for (int c = 0; c < nchunks; c++, cc++) {
            int buf = cc & 1;
            int pbase = base + (c << 4);    // 16 positions = 8 pairs
            u64* dst = &sm[buf][0][0];
            // load 23 rows x 8 pairs = 184 u64 with 128 threads (2 rounds)
            {
                int jr = t >> 3, i = t & 7;
                const float* rowp;
                if (jr < NRBF) rowp = g_rbf + jr * EP + pbase;
                else if (jr == 20) rowp = g_dirx + pbase;
                else if (jr == 21) rowp = g_diry + pbase;
                else rowp = g_dirz + pbase;
                dst[t] = *(const u64*)(rowp + (i << 1));
                if (t < 56) {
                    int q2 = t + 128;
                    int jr2 = q2 >> 3, i2 = q2 & 7;
                    const float* rowp2;
                    if (jr2 < NRBF) rowp2 = g_rbf + jr2 * EP + pbase;
                    else if (jr2 == 20) rowp2 = g_dirx + pbase;
                    else if (jr2 == 21) rowp2 = g_diry + pbase;
                    else rowp2 = g_dirz + pbase;
                    dst[q2] = *(const u64*)(rowp2 + (i2 << 1));
                }
            }
            __syncthreads();
            int i0 = c << 3;
            int nc = npairs - i0; if (nc > 8) nc = 8;
            for (int i = 0; i < nc; i++) {
                u64 x0 = br0d, x1 = br1d, x2 = br2d;
#pragma unroll
                for (int k = 0; k < NRBF; k++) {
                    u64 rr = sm[buf][k][i];
                    x0 = f2fma(rr, wr0d[k], x0);
                    x1 = f2fma(rr, wr1d[k], x1);
                    x2 = f2fma(rr, wr2d[k], x2);
                }
                float2 v0 = upk(x0), v1 = upk(x1), v2 = upk(x2);
                u64 W0 = pk2(cw(v0.x), cw(v0.y));
                u64 W1v = pk2(cw(v1.x), cw(v1.y));
                u64 W2v = pk2(cw(v2.x), cw(v2.y));
                u64 m = (((i0 + i) << 1) + 1 < cnt) ? ~0ull : 0xFFFFFFFFull;
                accA = f2add(accA, W0 & m);
                accB = f2add(accB, W1v & m);
                bx = f2fma(W2v, sm[buf][20][i], bx);
                by = f2fma(W2v, sm[buf][21][i], by);
                bz = f2fma(W2v, sm[buf][22][i], bz);
            }
        }
        float2 rA = upk(accA), rB = upk(accB);
        float2 rx = upk(bx), ry = upk(by), rz = upk(bz);
        float a1 = rA.x + rA.y;
        float a2 = rB.x + rB.y;
        float cx = rx.x + rx.y;
        float cy = ry.x + ry.y;
        float cz = rz.x + rz.y;

        float ph1 = g_phi[n * F3 + t];
        float ph2 = g_phi[n * F3 + FF + t];
        float ph3 = g_phi[n * F3 + 2 * FF + t];
        int nf = n * FF + t;
        float vx = v[nf * 3 + 0], vy = v[nf * 3 + 1], vz = v[nf * 3 + 2];
        float s1v = ph1 * a1;
        out[nf * 3 + 0] = fmaf(vx, s1v, ph3 * cx);
        out[nf * 3 + 1] = fmaf(vy, s1v, ph3 * cy);
        out[nf * 3 + 2] = fmaf(vz, s1v, ph3 * cz);
        out[NN * F3 + nf] = ph2 * a2;
    }
}

// ---------------- launch ----------------
extern "C" void kernel_launch(void* const* d_in, const int* in_sizes, int n_in,
                              void* d_out, int out_size) {
    (void)in_sizes; (void)n_in; (void)out_size;
    const float* v  = (const float*)d_in[0];
    const float* s  = (const float*)d_in[1];
    const float* r  = (const float*)d_in[2];
    const float* W1 = (const float*)d_in[3];
    const float* b1 = (const float*)d_in[4];
    const float* W2 = (const float*)d_in[5];
    const float* b2 = (const float*)d_in[6];
    const float* Wr = (const float*)d_in[7];
    const float* br = (const float*)d_in[8];
    float* out = (float*)d_out;

    cudaFuncSetAttribute(k_gemm_bf<true, true, 2>,
                         cudaFuncAttributeMaxDynamicSharedMemorySize, SMEM_B);
    cudaFuncSetAttribute(k_gemm_bf<false, false, 3>,
                         cudaFuncAttributeMaxDynamicSharedMemorySize, SMEM_B);

    void* q;
    uint32_t *sH, *sL, *hH, *hL, *w1H, *w1L, *w2H, *w2L;
    float* pphi;
    cudaGetSymbolAddress(&q, g_s2H);  sH  = (uint32_t*)q;
    cudaGetSymbolAddress(&q, g_s2L);  sL  = (uint32_t*)q;
    cudaGetSymbolAddress(&q, g_h2H);  hH  = (uint32_t*)q;
    cudaGetSymbolAddress(&q, g_h2L);  hL  = (uint32_t*)q;
    cudaGetSymbolAddress(&q, g_w1H2); w1H = (uint32_t*)q;
    cudaGetSymbolAddress(&q, g_w1L2); w1L = (uint32_t*)q;
    cudaGetSymbolAddress(&q, g_w2H2); w2H = (uint32_t*)q;
    cudaGetSymbolAddress(&q, g_w2L2); w2L = (uint32_t*)q;
    cudaGetSymbolAddress(&q, g_phi);  pphi = (float*)q;

    k_prepW<<<((FF + F3) * 64 + 255) / 256, 256>>>(W1, W2);
    k_prepS<<<(ROWS_PAD * 64 + 255) / 256, 256>>>(s);
    k_init<<<(EPAD + 255) / 256, 256>>>();
    // launch #4 = gemm1 (ncu capture slot)
    k_gemm_bf<true, true, 2><<<dim3(1, NTILE), 256, SMEM_B>>>(
        sH, sL, w1H, w1L, b1, hH, hL, nullptr, 0, NN);
    k_gemm_bf<false, false, 3><<<dim3(2, NTILE), 256, SMEM_B>>>(
        hH, hL, w2H, w2L, b2, nullptr, nullptr, pphi, F3, NN);
    k_hist<<<(EE + 255) / 256, 256>>>(r);
    k_scan<<<1, 1024>>>();
    k_fill<<<(EE + 255) / 256, 256>>>(r);
    k_sortlists<<<(NN + 127) / 128, 128>>>();
    k_edge<<<(EPAD + 127) / 128, 128>>>(r);
    k_main<<<4096, 128>>>(v, Wr, br, out);
}

// round 12
// speedup vs baseline: 1.8263x; 1.3081x over previous
#include <cuda_runtime.h>
#include <cuda_bf16.h>
#include <math.h>
#include <stdint.h>

#define NN 50000
#define EE 400000
#define FF 128
#define F3 384
#define NRBF 20
#define EPAD (EE + NN)
#define EP 450560
#define NTILE 391                 // ceil(50000/128)
#define ROWS_PAD (NTILE * 128)    // 50048
#define SMEM_U32 26112            // 2*(128*68) + 2*(64*68)
#define SMEM_B (SMEM_U32 * 4)     // 104448 bytes

typedef unsigned long long u64;

// ---------------- f32x2 packed helpers ----------------
__device__ __forceinline__ u64 pk2(float a, float b) {
    u64 r; asm("mov.b64 %0,{%1,%2};" : "=l"(r) : "f"(a), "f"(b)); return r;
}
__device__ __forceinline__ u64 pkdup(float a) {
    u64 r; asm("mov.b64 %0,{%1,%1};" : "=l"(r) : "f"(a)); return r;
}
__device__ __forceinline__ float2 upk(u64 v) {
    float2 f; asm("mov.b64 {%0,%1},%2;" : "=f"(f.x), "=f"(f.y) : "l"(v)); return f;
}
__device__ __forceinline__ u64 f2fma(u64 a, u64 b, u64 c) {
    u64 d; asm("fma.rn.f32x2 %0,%1,%2,%3;" : "=l"(d) : "l"(a), "l"(b), "l"(c)); return d;
}
__device__ __forceinline__ u64 f2add(u64 a, u64 b) {
    u64 d; asm("add.rn.f32x2 %0,%1,%2;" : "=l"(d) : "l"(a), "l"(b)); return d;
}

// ---------------- bf16 helpers ----------------
__device__ __forceinline__ uint32_t pack_bf2(__nv_bfloat16 lo, __nv_bfloat16 hi) {
    return ((uint32_t)__bfloat16_as_ushort(hi) << 16) | (uint32_t)__bfloat16_as_ushort(lo);
}
__device__ __forceinline__ void split2_pack(float v0, float v1, uint32_t& uh, uint32_t& ul) {
    __nv_bfloat16 h0 = __float2bfloat16(v0);
    __nv_bfloat16 h1 = __float2bfloat16(v1);
    __nv_bfloat16 l0 = __float2bfloat16(v0 - __bfloat162float(h0));
    __nv_bfloat16 l1 = __float2bfloat16(v1 - __bfloat162float(h1));
    uh = pack_bf2(h0, h1);
    ul = pack_bf2(l0, l1);
}
__device__ __forceinline__ void mma_bf16(float c[4], const uint32_t a[4],
                                         uint32_t b0, uint32_t b1) {
    asm volatile("mma.sync.aligned.m16n8k16.row.col.f32.bf16.bf16.f32 "
                 "{%0,%1,%2,%3},{%4,%5,%6,%7},{%8,%9},{%0,%1,%2,%3};"
                 : "+f"(c[0]), "+f"(c[1]), "+f"(c[2]), "+f"(c[3])
                 : "r"(a[0]), "r"(a[1]), "r"(a[2]), "r"(a[3]), "r"(b0), "r"(b1));
}

// ---------------- scratch ----------------
__device__ float g_phi[NN * F3];
__device__ float g_rbf[NRBF * EP];
__device__ float g_dirx[EP];
__device__ float g_diry[EP];
__device__ float g_dirz[EP];
__device__ int   g_cnt[NN];
__device__ int   g_off[NN];
__device__ int   g_cur[NN];
__device__ int   g_order[EPAD];
__device__ uint32_t g_s2H[ROWS_PAD * 64];
__device__ uint32_t g_s2L[ROWS_PAD * 64];
__device__ uint32_t g_h2H[ROWS_PAD * 64];
__device__ uint32_t g_h2L[ROWS_PAD * 64];
__device__ uint32_t g_w1H2[FF * 64];
__device__ uint32_t g_w1L2[FF * 64];
__device__ uint32_t g_w2H2[F3 * 64];
__device__ uint32_t g_w2L2[F3 * 64];

// ---------------- prep: weights -> W^T pair-packed bf16 hi/lo ----------------
__global__ void k_prepW(const float* __restrict__ W1, const float* __restrict__ W2) {
    int idx = blockIdx.x * blockDim.x + threadIdx.x;
    if (idx < FF * 64) {
        int n = idx >> 6, p = idx & 63;
        float v0 = W1[(2 * p) * FF + n];
        float v1 = W1[(2 * p + 1) * FF + n];
        uint32_t uh, ul; split2_pack(v0, v1, uh, ul);
        g_w1H2[idx] = uh; g_w1L2[idx] = ul;
    } else if (idx < (FF + F3) * 64) {
        int r = idx - FF * 64;
        int n = r >> 6, p = r & 63;
        float v0 = W2[(2 * p) * F3 + n];
        float v1 = W2[(2 * p + 1) * F3 + n];
        uint32_t uh, ul; split2_pack(v0, v1, uh, ul);
        g_w2H2[r] = uh; g_w2L2[r] = ul;
    }
}

// ---------------- prep: s -> pair-packed bf16 hi/lo (padded rows = 0) ----------------
__global__ void k_prepS(const float* __restrict__ s) {
    int idx = blockIdx.x * blockDim.x + threadIdx.x;
    if (idx >= ROWS_PAD * 64) return;
    int row = idx >> 6, p = idx & 63;
    float v0 = 0.f, v1 = 0.f;
    if (row < NN) {
        float2 q = *(const float2*)&s[row * FF + 2 * p];
        v0 = q.x; v1 = q.y;
    }
    uint32_t uh, ul; split2_pack(v0, v1, uh, ul);
    g_s2H[idx] = uh; g_s2L[idx] = ul;
}

// ---------------- 3xBF16 mma.sync GEMM (unchanged from R10) ----------------
template <bool SILU, bool OUTBF16, int NJ>
__global__ void __launch_bounds__(256) k_gemm_bf(const uint32_t* __restrict__ A2H,
                                                 const uint32_t* __restrict__ A2L,
                                                 const uint32_t* __restrict__ B2H,
                                                 const uint32_t* __restrict__ B2L,
                                                 const float* __restrict__ bias,
                                                 uint32_t* __restrict__ OH,
                                                 uint32_t* __restrict__ OL,
                                                 float* __restrict__ PHI,
                                                 int outN, int M) {
    extern __shared__ __align__(16) uint32_t smem[];
    uint32_t* sAh = smem;
    uint32_t* sAl = smem + 8704;
    uint32_t* sBh = smem + 17408;
    uint32_t* sBl = smem + 21760;

    int t = threadIdx.x;
    int lane = t & 31, wid = t >> 5;
    int warp_m = wid >> 1, warp_n = wid & 1;
    int lr = lane >> 2, lc = lane & 3;
    int rowBase = blockIdx.y * 128;

    {
        const uint4* gh = (const uint4*)(A2H + (size_t)rowBase * 64);
        const uint4* gl = (const uint4*)(A2L + (size_t)rowBase * 64);
#pragma unroll
        for (int sl = t; sl < 2048; sl += 256) {
            int row = sl >> 4, q = sl & 15;
            ((uint4*)(sAh + row * 68))[q] = gh[sl];
            ((uint4*)(sAl + row * 68))[q] = gl[sl];
        }
    }

#pragma unroll
    for (int jc = 0; jc < NJ; jc++) {
        int colBase = (blockIdx.x * NJ + jc) * 64;
        {
            const uint4* bh_ = (const uint4*)(B2H + (size_t)colBase * 64);
            const uint4* bl_ = (const uint4*)(B2L + (size_t)colBase * 64);
#pragma unroll
            for (int sl = t; sl < 1024; sl += 256) {
                int row = sl >> 4, q = sl & 15;
                ((uint4*)(sBh + row * 68))[q] = bh_[sl];
                ((uint4*)(sBl + row * 68))[q] = bl_[sl];
            }
        }
        __syncthreads();

        float acc[2][4][4];
#pragma unroll
        for (int i = 0; i < 2; i++)
#pragma unroll
            for (int j = 0; j < 4; j++)
#pragma unroll
                for (int q = 0; q < 4; q++) acc[i][j][q] = 0.0f;

#pragma unroll
        for (int ks = 0; ks < 8; ks++) {
            int c2 = lc + ks * 8;
            uint32_t ah[2][4], al[2][4];
#pragma unroll
            for (int i = 0; i < 2; i++) {
                int r0 = warp_m * 32 + i * 16 + lr;
                int b0 = r0 * 68;
                ah[i][0] = sAh[b0 + c2];
                ah[i][1] = sAh[b0 + 8 * 68 + c2];
                ah[i][2] = sAh[b0 + c2 + 4];
                ah[i][3] = sAh[b0 + 8 * 68 + c2 + 4];
                al[i][0] = sAl[b0 + c2];
                al[i][1] = sAl[b0 + 8 * 68 + c2];
                al[i][2] = sAl[b0 + c2 + 4];
                al[i][3] = sAl[b0 + 8 * 68 + c2 + 4];
            }
            uint32_t bh[4][2], bl[4][2];
#pragma unroll
            for (int j = 0; j < 4; j++) {
                int n0 = warp_n * 32 + j * 8 + lr;
                int bb = n0 * 68;
                bh[j][0] = sBh[bb + c2];
                bh[j][1] = sBh[bb + c2 + 4];
                bl[j][0] = sBl[bb + c2];
                bl[j][1] = sBl[bb + c2 + 4];
            }
#pragma unroll
            for (int i = 0; i < 2; i++)
#pragma unroll
                for (int j = 0; j < 4; j++) {
                    mma_bf16(acc[i][j], ah[i], bh[j][0], bh[j][1]);
                    mma_bf16(acc[i][j], ah[i], bl[j][0], bl[j][1]);
                    mma_bf16(acc[i][j], al[i], bh[j][0], bh[j][1]);
                }
        }

#pragma unroll
        for (int i = 0; i < 2; i++) {
#pragma unroll
            for (int j = 0; j < 4; j++) {
                int col0 = warp_n * 32 + j * 8 + lc * 2;
                int gcol = colBase + col0;
                float b0 = bias[gcol], b1 = bias[gcol + 1];
#pragma unroll
                for (int h = 0; h < 2; h++) {
                    int grow = rowBase + warp_m * 32 + i * 16 + lr + h * 8;
                    float v0 = acc[i][j][2 * h] + b0;
                    float v1 = acc[i][j][2 * h + 1] + b1;
                    if (SILU) {
                        v0 = v0 / (1.0f + __expf(-v0));
                        v1 = v1 / (1.0f + __expf(-v1));
                    }
                    if (OUTBF16) {
                        uint32_t uh, ul; split2_pack(v0, v1, uh, ul);
                        int oi = grow * 64 + (gcol >> 1);
                        OH[oi] = uh; OL[oi] = ul;
                    } else {
                        if (grow < M)
                            *(float2*)&PHI[(size_t)grow * outN + gcol] = make_float2(v0, v1);
                    }
                }
            }
        }
        __syncthreads();
    }
}

// ---------------- CSR build ----------------
__global__ void k_init() {
    int i = blockIdx.x * blockDim.x + threadIdx.x;
    if (i < NN) g_cnt[i] = 0;
    if (i < EPAD) g_order[i] = -1;
}

__global__ void k_hist(const float* __restrict__ r) {
    int e = blockIdx.x * blockDim.x + threadIdx.x;
    if (e < EE) {
        int jn = (int)r[e * 5 + 1];
        atomicAdd(&g_cnt[jn], 1);
    }
}

__global__ void k_scan() {
    __shared__ int part[1024];
    int t = threadIdx.x;
    const int CH = (NN + 1023) / 1024;
    int base = t * CH, sum = 0;
    for (int i = 0; i < CH; i++) {
        int idx = base + i;
        if (idx < NN) sum += (g_cnt[idx] + 1) & ~1;
    }
    part[t] = sum;
    __syncthreads();
    for (int off = 1; off < 1024; off <<= 1) {
        int v = (t >= off) ? part[t - off] : 0;
        __syncthreads();
        part[t] += v;
        __syncthreads();
    }
    int run = (t > 0) ? part[t - 1] : 0;
    for (int i = 0; i < CH; i++) {
        int idx = base + i;
        if (idx < NN) {
            g_off[idx] = run;
            g_cur[idx] = run;
            run += (g_cnt[idx] + 1) & ~1;
        }
    }
}

__global__ void k_fill(const float* __restrict__ r) {
    int e = blockIdx.x * blockDim.x + threadIdx.x;
    if (e < EE) {
        int jn = (int)r[e * 5 + 1];
        int pos = atomicAdd(&g_cur[jn], 1);
        g_order[pos] = e;
    }
}

__global__ void k_sortlists() {
    int n = blockIdx.x * blockDim.x + threadIdx.x;
    if (n >= NN) return;
    int s0 = g_off[n], s1 = s0 + g_cnt[n];
    for (int i = s0 + 1; i < s1; i++) {
        int key = g_order[i];
        int jj = i - 1;
        while (jj >= s0 && g_order[jj] > key) {
            g_order[jj + 1] = g_order[jj];
            jj--;
        }
        g_order[jj + 1] = key;
    }
}

// ---------------- per-edge precompute ----------------
__global__ void k_edge(const float* __restrict__ r) {
    int p = blockIdx.x * blockDim.x + threadIdx.x;
    if (p >= EPAD) return;
    int eid = g_order[p];
    if (eid < 0) {
#pragma unroll
        for (int k = 0; k < NRBF; k++) g_rbf[k * EP + p] = 0.0f;
        g_dirx[p] = 0.0f; g_diry[p] = 0.0f; g_dirz[p] = 0.0f;
        return;
    }
    float rx = r[eid * 5 + 2];
    float ry = r[eid * 5 + 3];
    float rz = r[eid * 5 + 4];
    float z = fabsf(rz);
    float inv = 1.0f / (z + 1e-8f);
    float th = 0.6283185307179586f * z;
    float s, c;
    sincosf(th, &s, &c);
    float twoc = 2.0f * c;
    float skm = 0.0f, sk = s;
#pragma unroll
    for (int k = 0; k < NRBF; k++) {
        g_rbf[k * EP + p] = sk * inv;
        float nxt = fmaf(twoc, sk, -skm);
        skm = sk; sk = nxt;
    }
    float nrm = sqrtf(rx * rx + ry * ry + rz * rz);
    float invn = 1.0f / (nrm + 1e-8f);
    g_dirx[p] = rx * invn;
    g_diry[p] = ry * invn;
    g_dirz[p] = rz * invn;
}

// ---------------- cutoff via MUFU ----------------
__device__ __forceinline__ float cw(float x) {
    float c = __cosf(x * 0.6283185307179586f);
    float w = fmaf(c, 0.5f, 0.5f);
    return (x < 5.0f) ? w : 0.0f;
}

// ---------------- main per-node kernel: register-prefetch chunk pipeline ----------------
// chunk = up to 8 edge pairs of one node; loop: STS(prefetched) -> LDG(next) -> sync -> compute
__global__ void __launch_bounds__(128) k_main(const float* __restrict__ v,
                                              const float* __restrict__ Wr,
                                              const float* __restrict__ br,
                                              float* __restrict__ out) {
    __shared__ u64 sm[2][23][8];
    int t = threadIdx.x;

    u64 wr0d[NRBF], wr1d[NRBF], wr2d[NRBF];
#pragma unroll
    for (int k = 0; k < NRBF; k++) {
        wr0d[k] = pkdup(Wr[k * F3 + t]);
        wr1d[k] = pkdup(Wr[k * F3 + FF + t]);
        wr2d[k] = pkdup(Wr[k * F3 + 2 * FF + t]);
    }
    u64 br0d = pkdup(br[t]), br1d = pkdup(br[FF + t]), br2d = pkdup(br[2 * FF + t]);

    // per-thread prefetch source row pointers (row index fixed per thread)
    int jr0 = t >> 3, i0x = t & 7;
    int jr1 = (t + 128) >> 3, i1x = (t + 128) & 7;
    const float* rowbase0 =
        (jr0 < NRBF) ? (g_rbf + jr0 * EP) :
        (jr0 == 20) ? g_dirx : (jr0 == 21) ? g_diry : g_dirz;
    const float* rowbase1 =
        (jr1 < NRBF) ? (g_rbf + jr1 * EP) :
        (jr1 == 20) ? g_dirx : (jr1 == 21) ? g_diry : g_dirz;
    bool has2 = (t < 56);

    int cur_n = blockIdx.x;
    if (cur_n >= NN) return;
    int cur_c = 0;
    int cur_cnt = g_cnt[cur_n];
    int cur_base = g_off[cur_n];

    // prologue prefetch: chunk (cur_n, 0)
    u64 pr0, pr1 = 0ull;
    {
        int pbase = cur_base;
        pr0 = *(const u64*)(rowbase0 + pbase + (i0x << 1));
        if (has2) pr1 = *(const u64*)(rowbase1 + pbase + (i1x << 1));
    }

    u64 accA = 0ull, accB = 0ull, bx = 0ull, by = 0ull, bz = 0ull;
    int buf = 0;

    while (true) {
        // store prefetched chunk into smem
        u64* dst = &sm[buf][0][0];
        dst[t] = pr0;
        if (has2) dst[t + 128] = pr1;

        // compute next chunk coords and issue its LDG before the barrier
        int npairs = (cur_cnt + 1) >> 1;
        int nchunks = (npairs + 7) >> 3;          // 0 for degree-0 node
        bool last_of_node = (cur_c + 1 >= nchunks);
        int nxt_n, nxt_c, nxt_cnt = 0, nxt_base = 0;
        if (!last_of_node) {
            nxt_n = cur_n; nxt_c = cur_c + 1; nxt_cnt = cur_cnt; nxt_base = cur_base;
        } else {
            nxt_n = cur_n + gridDim.x; nxt_c = 0;
            if (nxt_n < NN) {
                nxt_cnt = g_cnt[nxt_n];
                nxt_base = g_off[nxt_n];
            }
        }
        if (nxt_n < NN) {
            int pbase = nxt_base + (nxt_c << 4);
            pr0 = *(const u64*)(rowbase0 + pbase + (i0x << 1));
            if (has2) pr1 = *(const u64*)(rowbase1 + pbase + (i1x << 1));
        }
        __syncthreads();

        // compute current chunk
        int pi0 = cur_c << 3;
        int nc = npairs - pi0; if (nc > 8) nc = 8; if (nc < 0) nc = 0;
        for (int i = 0; i < nc; i++) {
            u64 x0 = br0d, x1 = br1d, x2 = br2d;
#pragma unroll
            for (int k = 0; k < NRBF; k++) {
                u64 rr = sm[buf][k][i];
                x0 = f2fma(rr, wr0d[k], x0);
                x1 = f2fma(rr, wr1d[k], x1);
                x2 = f2fma(rr, wr2d[k], x2);
            }
            float2 v0 = upk(x0), v1 = upk(x1), v2 = upk(x2);
            u64 W0 = pk2(cw(v0.x), cw(v0.y));
            u64 W1v = pk2(cw(v1.x), cw(v1.y));
            u64 W2v = pk2(cw(v2.x), cw(v2.y));
            u64 m = (((pi0 + i) << 1) + 1 < cur_cnt) ? ~0ull : 0xFFFFFFFFull;
            accA = f2add(accA, W0 & m);
            accB = f2add(accB, W1v & m);
            bx = f2fma(W2v, sm[buf][20][i], bx);
            by = f2fma(W2v, sm[buf][21][i], by);
            bz = f2fma(W2v, sm[buf][22][i], bz);
        }
        buf ^= 1;

        if (last_of_node) {
            // node epilogue
            float2 rA = upk(accA), rB = upk(accB);
            float2 rx = upk(bx), ry = upk(by), rz = upk(bz);
            float a1 = rA.x + rA.y;
            float a2 = rB.x + rB.y;
            float cx = rx.x + rx.y;
            float cy = ry.x + ry.y;
            float cz = rz.x + rz.y;

            float ph1 = g_phi[cur_n * F3 + t];
            float ph2 = g_phi[cur_n * F3 + FF + t];
            float ph3 = g_phi[cur_n * F3 + 2 * FF + t];
            int nf = cur_n * FF + t;
            float vx = v[nf * 3 + 0], vy = v[nf * 3 + 1], vz = v[nf * 3 + 2];
            float s1v = ph1 * a1;
            out[nf * 3 + 0] = fmaf(vx, s1v, ph3 * cx);
            out[nf * 3 + 1] = fmaf(vy, s1v, ph3 * cy);
            out[nf * 3 + 2] = fmaf(vz, s1v, ph3 * cz);
            out[NN * F3 + nf] = ph2 * a2;
            accA = accB = bx = by = bz = 0ull;
        }

        if (nxt_n >= NN) break;
        cur_n = nxt_n; cur_c = nxt_c; cur_cnt = nxt_cnt; cur_base = nxt_base;
    }
}

// ---------------- launch ----------------
extern "C" void kernel_launch(void* const* d_in, const int* in_sizes, int n_in,
                              void* d_out, int out_size) {
    (void)in_sizes; (void)n_in; (void)out_size;
    const float* v  = (const float*)d_in[0];
    const float* s  = (const float*)d_in[1];
    const float* r  = (const float*)d_in[2];
    const float* W1 = (const float*)d_in[3];
    const float* b1 = (const float*)d_in[4];
    const float* W2 = (const float*)d_in[5];
    const float* b2 = (const float*)d_in[6];
    const float* Wr = (const float*)d_in[7];
    const float* br = (const float*)d_in[8];
    float* out = (float*)d_out;

    cudaFuncSetAttribute(k_gemm_bf<true, true, 2>,
                         cudaFuncAttributeMaxDynamicSharedMemorySize, SMEM_B);
    cudaFuncSetAttribute(k_gemm_bf<false, false, 3>,
                         cudaFuncAttributeMaxDynamicSharedMemorySize, SMEM_B);

    void* q;
    uint32_t *sH, *sL, *hH, *hL, *w1H, *w1L, *w2H, *w2L;
    float* pphi;
    cudaGetSymbolAddress(&q, g_s2H);  sH  = (uint32_t*)q;
    cudaGetSymbolAddress(&q, g_s2L);  sL  = (uint32_t*)q;
    cudaGetSymbolAddress(&q, g_h2H);  hH  = (uint32_t*)q;
    cudaGetSymbolAddress(&q, g_h2L);  hL  = (uint32_t*)q;
    cudaGetSymbolAddress(&q, g_w1H2); w1H = (uint32_t*)q;
    cudaGetSymbolAddress(&q, g_w1L2); w1L = (uint32_t*)q;
    cudaGetSymbolAddress(&q, g_w2H2); w2H = (uint32_t*)q;
    cudaGetSymbolAddress(&q, g_w2L2); w2L = (uint32_t*)q;
    cudaGetSymbolAddress(&q, g_phi);  pphi = (float*)q;

    k_prepW<<<((FF + F3) * 64 + 255) / 256, 256>>>(W1, W2);
    k_prepS<<<(ROWS_PAD * 64 + 255) / 256, 256>>>(s);
    k_gemm_bf<true, true, 2><<<dim3(1, NTILE), 256, SMEM_B>>>(
        sH, sL, w1H, w1L, b1, hH, hL, nullptr, 0, NN);
    // launch #4 = gemm2 (ncu capture slot this round)
    k_gemm_bf<false, false, 3><<<dim3(2, NTILE), 256, SMEM_B>>>(
        hH, hL, w2H, w2L, b2, nullptr, nullptr, pphi, F3, NN);
    k_init<<<(EPAD + 255) / 256, 256>>>();
    k_hist<<<(EE + 255) / 256, 256>>>(r);
    k_scan<<<1, 1024>>>();
    k_fill<<<(EE + 255) / 256, 256>>>(r);
    k_sortlists<<<(NN + 127) / 128, 128>>>();
    k_edge<<<(EPAD + 127) / 128, 128>>>(r);
    k_main<<<4096, 128>>>(v, Wr, br, out);
}